// round 3
// baseline (speedup 1.0000x reference)
#include <cuda_runtime.h>
#include <cstdint>

#define N_NODES 100000
#define N_EDGES 3200000
#define IN_F    1433
#define HID     16
#define OUTF    7
#define OUTP    8   // padded out width for vector reds

// ---------------- scratch (static device globals; no allocation) ------------
__device__ __align__(16) float g_norm_src[N_NODES];          // deg_out -> rsqrt
__device__ __align__(16) float g_norm_dst[N_NODES];          // deg_in  -> rsqrt
__device__ __align__(16) float g_x1  [N_NODES * HID];        // (X*ns)@W1
__device__ __align__(16) float g_agg1[N_NODES * HID];        // scatter-sum 1
__device__ __align__(16) float g_x2  [N_NODES * OUTP];       // (h*ns)@W2, padded
__device__ __align__(16) float g_agg2[N_NODES * OUTP];       // scatter-sum 2
__device__ int g_is64;                                       // edge dtype flag

// ---------------- small PTX helpers ----------------------------------------
__device__ __forceinline__ unsigned long long pk2(float lo, float hi) {
    unsigned long long r;
    asm("mov.b64 %0, {%1, %2};" : "=l"(r) : "f"(lo), "f"(hi));
    return r;
}
__device__ __forceinline__ float2 upk2(unsigned long long v) {
    float2 f;
    asm("mov.b64 {%0, %1}, %2;" : "=f"(f.x), "=f"(f.y) : "l"(v));
    return f;
}
__device__ __forceinline__ void fma2(unsigned long long& a,
                                     unsigned long long x,
                                     unsigned long long w) {
    asm("fma.rn.f32x2 %0, %1, %2, %0;" : "+l"(a) : "l"(x), "l"(w));
}
__device__ __forceinline__ void red_v4(float* p, float4 v) {
    asm volatile("red.global.add.v4.f32 [%0], {%1, %2, %3, %4};"
                 :: "l"(p), "f"(v.x), "f"(v.y), "f"(v.z), "f"(v.w) : "memory");
}

// ---------------- kernels ---------------------------------------------------
__global__ void zero_kernel() {
    int i = blockIdx.x * blockDim.x + threadIdx.x;
    int stride = gridDim.x * blockDim.x;
    float4 z = make_float4(0.f, 0.f, 0.f, 0.f);
    for (int j = i; j < N_NODES / 4; j += stride) {
        reinterpret_cast<float4*>(g_norm_src)[j] = z;
        reinterpret_cast<float4*>(g_norm_dst)[j] = z;
    }
    for (int j = i; j < N_NODES * HID / 4; j += stride)
        reinterpret_cast<float4*>(g_agg1)[j] = z;
    for (int j = i; j < N_NODES * OUTP / 4; j += stride)
        reinterpret_cast<float4*>(g_agg2)[j] = z;
}

// Detect whether edge_index is genuinely int64 or int32 stored as int32.
// int64 values are < 1e5 << 2^32; int32 pairs reinterpreted as int64 are
// >= 2^32 unless the high half is 0 (prob ~1e-5 per pair; check 16).
__global__ void detect_kernel(const unsigned long long* __restrict__ ei) {
    unsigned long long mx = 0;
#pragma unroll
    for (int i = 0; i < 16; i++) mx = mx < ei[i] ? ei[i] : mx;
    g_is64 = (mx < (1ull << 32)) ? 1 : 0;
}

__device__ __forceinline__ void load_edge(const long long* ei, int e,
                                          int& s, int& d) {
    if (g_is64) {
        s = (int)ei[e];
        d = (int)ei[N_EDGES + e];
    } else {
        const int* e32 = reinterpret_cast<const int*>(ei);
        s = e32[e];
        d = e32[N_EDGES + e];
    }
}

__global__ void degree_kernel(const long long* __restrict__ ei) {
    int e = blockIdx.x * blockDim.x + threadIdx.x;
    if (e >= N_EDGES) return;
    int s, d;
    load_edge(ei, e, s, d);
    atomicAdd(g_norm_src + s, 1.f);
    atomicAdd(g_norm_dst + d, 1.f);
}

__global__ void norm_kernel() {
    int i = blockIdx.x * blockDim.x + threadIdx.x;
    if (i >= N_NODES) return;
    g_norm_src[i] = rsqrtf(fmaxf(g_norm_src[i], 1.f));
    g_norm_dst[i] = rsqrtf(fmaxf(g_norm_dst[i], 1.f));
}

// x1[r][0:16] = norm_src[r] * (feat[r,:] @ W1)
// CTA = 256 threads = 8 warps; warp covers 64 rows (lane = row, 2 rows/lane).
// W1 (1433x16 = 91.7KB) in dynamic smem; per-k reads are warp-broadcast LDS.64.
__global__ void gemm1_kernel(const float* __restrict__ feat,
                             const float* __restrict__ W1) {
    extern __shared__ float sW[];  // IN_F * HID floats
    for (int i = threadIdx.x; i < IN_F * HID / 4; i += blockDim.x)
        reinterpret_cast<float4*>(sW)[i] =
            reinterpret_cast<const float4*>(W1)[i];
    __syncthreads();

    int warp = threadIdx.x >> 5, lane = threadIdx.x & 31;
    int r0 = blockIdx.x * 512 + warp * 64 + lane;
    int r1 = r0 + 32;
    bool v0 = r0 < N_NODES, v1 = r1 < N_NODES;
    const float* f0 = feat + (long long)r0 * IN_F;
    const float* f1 = feat + (long long)r1 * IN_F;

    unsigned long long a0[8], a1[8];
#pragma unroll
    for (int j = 0; j < 8; j++) { a0[j] = 0ull; a1[j] = 0ull; }

#pragma unroll 4
    for (int k = 0; k < IN_F; k++) {
        float x0 = v0 ? __ldg(f0 + k) : 0.f;
        float x1 = v1 ? __ldg(f1 + k) : 0.f;
        unsigned long long p0 = pk2(x0, x0);
        unsigned long long p1 = pk2(x1, x1);
        const float2* wk = reinterpret_cast<const float2*>(sW + k * HID);
#pragma unroll
        for (int j = 0; j < 8; j++) {
            float2 w = wk[j];
            unsigned long long wp = pk2(w.x, w.y);
            fma2(a0[j], p0, wp);
            fma2(a1[j], p1, wp);
        }
    }

    if (v0) {
        float ns = g_norm_src[r0];
        float4* o = reinterpret_cast<float4*>(g_x1 + (long long)r0 * HID);
#pragma unroll
        for (int jj = 0; jj < 4; jj++) {
            float2 e0 = upk2(a0[2 * jj]), e1 = upk2(a0[2 * jj + 1]);
            o[jj] = make_float4(e0.x * ns, e0.y * ns, e1.x * ns, e1.y * ns);
        }
    }
    if (v1) {
        float ns = g_norm_src[r1];
        float4* o = reinterpret_cast<float4*>(g_x1 + (long long)r1 * HID);
#pragma unroll
        for (int jj = 0; jj < 4; jj++) {
            float2 e0 = upk2(a1[2 * jj]), e1 = upk2(a1[2 * jj + 1]);
            o[jj] = make_float4(e0.x * ns, e0.y * ns, e1.x * ns, e1.y * ns);
        }
    }
}

__global__ void scatter1_kernel(const long long* __restrict__ ei) {
    int e = blockIdx.x * blockDim.x + threadIdx.x;
    if (e >= N_EDGES) return;
    int s, d;
    load_edge(ei, e, s, d);
    const float4* xs = reinterpret_cast<const float4*>(g_x1 + (long long)s * HID);
    float4 v0 = xs[0], v1 = xs[1], v2 = xs[2], v3 = xs[3];
    float* b = g_agg1 + (long long)d * HID;
    red_v4(b + 0, v0);
    red_v4(b + 4, v1);
    red_v4(b + 8, v2);
    red_v4(b + 12, v3);
}

// h = relu(agg1*nd + b1); x2 = (h*ns) @ W2 (padded to 8, col 7 = 0)
__global__ void post1_kernel(const float* __restrict__ b1,
                             const float* __restrict__ W2) {
    __shared__ float sW2[HID * OUTF];
    __shared__ float sb1[HID];
    if (threadIdx.x < HID * OUTF) sW2[threadIdx.x] = W2[threadIdx.x];
    if (threadIdx.x < HID) sb1[threadIdx.x] = b1[threadIdx.x];
    __syncthreads();

    int i = blockIdx.x * blockDim.x + threadIdx.x;
    if (i >= N_NODES) return;
    float nd = g_norm_dst[i], ns = g_norm_src[i];
    const float4* ag = reinterpret_cast<const float4*>(g_agg1 + (long long)i * HID);
    float h[HID];
#pragma unroll
    for (int q = 0; q < 4; q++) {
        float4 v = ag[q];
        h[4 * q + 0] = fmaxf(v.x * nd + sb1[4 * q + 0], 0.f) * ns;
        h[4 * q + 1] = fmaxf(v.y * nd + sb1[4 * q + 1], 0.f) * ns;
        h[4 * q + 2] = fmaxf(v.z * nd + sb1[4 * q + 2], 0.f) * ns;
        h[4 * q + 3] = fmaxf(v.w * nd + sb1[4 * q + 3], 0.f) * ns;
    }
    float o[OUTP];
#pragma unroll
    for (int j = 0; j < OUTP; j++) o[j] = 0.f;
#pragma unroll
    for (int k = 0; k < HID; k++) {
        float hv = h[k];
#pragma unroll
        for (int j = 0; j < OUTF; j++) o[j] += hv * sW2[k * OUTF + j];
    }
    float4* xo = reinterpret_cast<float4*>(g_x2 + (long long)i * OUTP);
    xo[0] = make_float4(o[0], o[1], o[2], o[3]);
    xo[1] = make_float4(o[4], o[5], o[6], 0.f);
}

__global__ void scatter2_kernel(const long long* __restrict__ ei) {
    int e = blockIdx.x * blockDim.x + threadIdx.x;
    if (e >= N_EDGES) return;
    int s, d;
    load_edge(ei, e, s, d);
    const float4* xs = reinterpret_cast<const float4*>(g_x2 + (long long)s * OUTP);
    float4 v0 = xs[0], v1 = xs[1];
    float* b = g_agg2 + (long long)d * OUTP;
    red_v4(b + 0, v0);
    red_v4(b + 4, v1);
}

__global__ void out_kernel(float* __restrict__ out,
                           const float* __restrict__ b2) {
    int idx = blockIdx.x * blockDim.x + threadIdx.x;
    if (idx >= N_NODES * OUTF) return;
    int node = idx / OUTF;
    int j = idx - node * OUTF;
    out[idx] = g_agg2[node * OUTP + j] * g_norm_dst[node] + b2[j];
}

// ---------------- launch -----------------------------------------------------
extern "C" void kernel_launch(void* const* d_in, const int* in_sizes, int n_in,
                              void* d_out, int out_size) {
    const float* feat = (const float*)d_in[0];
    const long long* ei = (const long long*)d_in[1];
    const float* W1 = (const float*)d_in[2];
    const float* b1 = (const float*)d_in[3];
    const float* W2 = (const float*)d_in[4];
    const float* b2 = (const float*)d_in[5];
    float* out = (float*)d_out;

    (void)in_sizes; (void)n_in; (void)out_size;

    zero_kernel<<<960, 256>>>();
    detect_kernel<<<1, 1>>>((const unsigned long long*)ei);
    degree_kernel<<<(N_EDGES + 255) / 256, 256>>>(ei);
    norm_kernel<<<(N_NODES + 255) / 256, 256>>>();

    const int smem = IN_F * HID * 4;  // 91712 B
    cudaFuncSetAttribute(gemm1_kernel,
                         cudaFuncAttributeMaxDynamicSharedMemorySize, smem);
    gemm1_kernel<<<(N_NODES + 511) / 512, 256, smem>>>(feat, W1);

    scatter1_kernel<<<(N_EDGES + 255) / 256, 256>>>(ei);
    post1_kernel<<<(N_NODES + 255) / 256, 256>>>(b1, W2);
    scatter2_kernel<<<(N_EDGES + 255) / 256, 256>>>(ei);
    out_kernel<<<(N_NODES * OUTF + 255) / 256, 256>>>(out, b2);
}

// round 6
// speedup vs baseline: 2.5285x; 2.5285x over previous
#include <cuda_runtime.h>
#include <cstdint>

#define N_NODES 100000
#define N_EDGES 3200000
#define IN_F    1433
#define HID     16
#define OUTF    7
#define OUTP    8   // padded out width for vector reds

#define G1_THREADS 512
#define G1_ROWS    676   // rows per CTA; 148 * 676 = 100048 >= N_NODES
#define G1_GRID    148

// ---------------- scratch (static device globals; no allocation) ------------
__device__ __align__(16) float g_norm_src[N_NODES];          // deg_out -> rsqrt
__device__ __align__(16) float g_norm_dst[N_NODES];          // deg_in  -> rsqrt
__device__ __align__(16) float g_x1  [N_NODES * HID];        // (X*ns)@W1
__device__ __align__(16) float g_agg1[N_NODES * HID];        // scatter-sum 1
__device__ __align__(16) float g_x2  [N_NODES * OUTP];       // (h*ns)@W2, padded
__device__ __align__(16) float g_agg2[N_NODES * OUTP];       // scatter-sum 2
__device__ int g_is64;                                       // edge dtype flag

// ---------------- small PTX helpers ----------------------------------------
__device__ __forceinline__ unsigned long long pk2(float lo, float hi) {
    unsigned long long r;
    asm("mov.b64 %0, {%1, %2};" : "=l"(r) : "f"(lo), "f"(hi));
    return r;
}
__device__ __forceinline__ float2 upk2(unsigned long long v) {
    float2 f;
    asm("mov.b64 {%0, %1}, %2;" : "=f"(f.x), "=f"(f.y) : "l"(v));
    return f;
}
__device__ __forceinline__ void fma2(unsigned long long& a,
                                     unsigned long long x,
                                     unsigned long long w) {
    asm("fma.rn.f32x2 %0, %1, %2, %0;" : "+l"(a) : "l"(x), "l"(w));
}
__device__ __forceinline__ void red_v4(float* p, float4 v) {
    asm volatile("red.global.add.v4.f32 [%0], {%1, %2, %3, %4};"
                 :: "l"(p), "f"(v.x), "f"(v.y), "f"(v.z), "f"(v.w) : "memory");
}

// ---------------- kernels ---------------------------------------------------
__global__ void zero_kernel() {
    int i = blockIdx.x * blockDim.x + threadIdx.x;
    int stride = gridDim.x * blockDim.x;
    float4 z = make_float4(0.f, 0.f, 0.f, 0.f);
    for (int j = i; j < N_NODES / 4; j += stride) {
        reinterpret_cast<float4*>(g_norm_src)[j] = z;
        reinterpret_cast<float4*>(g_norm_dst)[j] = z;
    }
    for (int j = i; j < N_NODES * HID / 4; j += stride)
        reinterpret_cast<float4*>(g_agg1)[j] = z;
    for (int j = i; j < N_NODES * OUTP / 4; j += stride)
        reinterpret_cast<float4*>(g_agg2)[j] = z;
}

// Detect whether edge_index is genuinely int64 or int32 (JAX x64 disabled).
__global__ void detect_kernel(const unsigned long long* __restrict__ ei) {
    unsigned long long mx = 0;
#pragma unroll
    for (int i = 0; i < 16; i++) mx = mx < ei[i] ? ei[i] : mx;
    g_is64 = (mx < (1ull << 32)) ? 1 : 0;
}

__device__ __forceinline__ void load_edge(const long long* ei, int e,
                                          int& s, int& d) {
    if (g_is64) {
        s = (int)ei[e];
        d = (int)ei[N_EDGES + e];
    } else {
        const int* e32 = reinterpret_cast<const int*>(ei);
        s = e32[e];
        d = e32[N_EDGES + e];
    }
}

__global__ void degree_kernel(const long long* __restrict__ ei) {
    int e = blockIdx.x * blockDim.x + threadIdx.x;
    if (e >= N_EDGES) return;
    int s, d;
    load_edge(ei, e, s, d);
    atomicAdd(g_norm_src + s, 1.f);
    atomicAdd(g_norm_dst + d, 1.f);
}

__global__ void norm_kernel() {
    int i = blockIdx.x * blockDim.x + threadIdx.x;
    if (i >= N_NODES) return;
    g_norm_src[i] = rsqrtf(fmaxf(g_norm_src[i], 1.f));
    g_norm_dst[i] = rsqrtf(fmaxf(g_norm_dst[i], 1.f));
}

// -------- gemm1: x1[r][0:16] = norm_src[r] * (feat[r,:] @ W1) ---------------
// 148 CTAs (1/SM, single wave, equal rows/SM), 512 threads, W1 in smem.
// Feature rows loaded as float4 with per-row alignment peel (row phase = r&3).

__device__ __forceinline__ void body_k1(float x0, const float4* wk,
                                        unsigned long long* a0) {
    unsigned long long p0 = pk2(x0, x0);
#pragma unroll
    for (int q = 0; q < 4; q++) {
        float4 w = wk[q];
        unsigned long long wa = pk2(w.x, w.y);
        unsigned long long wb = pk2(w.z, w.w);
        fma2(a0[2 * q], p0, wa);
        fma2(a0[2 * q + 1], p0, wb);
    }
}
__device__ __forceinline__ void body_k2(float x0, float x1, const float4* wk,
                                        unsigned long long* a0,
                                        unsigned long long* a1) {
    unsigned long long p0 = pk2(x0, x0);
    unsigned long long p1 = pk2(x1, x1);
#pragma unroll
    for (int q = 0; q < 4; q++) {
        float4 w = wk[q];
        unsigned long long wa = pk2(w.x, w.y);
        unsigned long long wb = pk2(w.z, w.w);
        fma2(a0[2 * q], p0, wa);
        fma2(a0[2 * q + 1], p0, wb);
        fma2(a1[2 * q], p1, wa);
        fma2(a1[2 * q + 1], p1, wb);
    }
}

__device__ __forceinline__ void store_row(int r, unsigned long long* a) {
    float ns = g_norm_src[r];
    float4* o = reinterpret_cast<float4*>(g_x1 + (long long)r * HID);
#pragma unroll
    for (int jj = 0; jj < 4; jj++) {
        float2 e0 = upk2(a[2 * jj]), e1 = upk2(a[2 * jj + 1]);
        o[jj] = make_float4(e0.x * ns, e0.y * ns, e1.x * ns, e1.y * ns);
    }
}

__global__ void __launch_bounds__(G1_THREADS, 1)
gemm1_kernel(const float* __restrict__ feat, const float* __restrict__ W1) {
    extern __shared__ float sW[];  // IN_F * HID floats = 91712 B
    for (int i = threadIdx.x; i < IN_F * HID / 4; i += G1_THREADS)
        reinterpret_cast<float4*>(sW)[i] =
            reinterpret_cast<const float4*>(W1)[i];
    __syncthreads();

    const int base = blockIdx.x * G1_ROWS;
    const int row_end = min(base + G1_ROWS, N_NODES);
    const int r0 = base + threadIdx.x;
    const int r1 = base + G1_THREADS + threadIdx.x;
    const bool v0 = r0 < row_end;
    const bool v1 = r1 < row_end;
    if (!v0) return;

    // row byte-offset mod 16 depends only on r mod 4 (1433 odd); r1-r0=512≡0 (4)
    const int peel = (4 - (r0 & 3)) & 3;

    if (v1) {
        const float* f0 = feat + (long long)r0 * IN_F;
        const float* f1 = feat + (long long)r1 * IN_F;
        unsigned long long a0[8], a1[8];
#pragma unroll
        for (int j = 0; j < 8; j++) { a0[j] = 0ull; a1[j] = 0ull; }
        int k = 0;
        for (; k < peel; k++)
            body_k2(f0[k], f1[k], (const float4*)(sW + k * HID), a0, a1);
        const int main4 = (IN_F - peel) >> 2;
        const float4* g0 = reinterpret_cast<const float4*>(f0 + peel);
        const float4* g1 = reinterpret_cast<const float4*>(f1 + peel);
#pragma unroll 2
        for (int m = 0; m < main4; m++) {
            float4 x0 = __ldg(g0 + m);
            float4 x1 = __ldg(g1 + m);
            int kk = peel + 4 * m;
            body_k2(x0.x, x1.x, (const float4*)(sW + (kk + 0) * HID), a0, a1);
            body_k2(x0.y, x1.y, (const float4*)(sW + (kk + 1) * HID), a0, a1);
            body_k2(x0.z, x1.z, (const float4*)(sW + (kk + 2) * HID), a0, a1);
            body_k2(x0.w, x1.w, (const float4*)(sW + (kk + 3) * HID), a0, a1);
        }
        for (k = peel + 4 * main4; k < IN_F; k++)
            body_k2(f0[k], f1[k], (const float4*)(sW + k * HID), a0, a1);
        store_row(r0, a0);
        store_row(r1, a1);
    } else {
        const float* f0 = feat + (long long)r0 * IN_F;
        unsigned long long a0[8];
#pragma unroll
        for (int j = 0; j < 8; j++) a0[j] = 0ull;
        int k = 0;
        for (; k < peel; k++)
            body_k1(f0[k], (const float4*)(sW + k * HID), a0);
        const int main4 = (IN_F - peel) >> 2;
        const float4* g0 = reinterpret_cast<const float4*>(f0 + peel);
#pragma unroll 2
        for (int m = 0; m < main4; m++) {
            float4 x0 = __ldg(g0 + m);
            int kk = peel + 4 * m;
            body_k1(x0.x, (const float4*)(sW + (kk + 0) * HID), a0);
            body_k1(x0.y, (const float4*)(sW + (kk + 1) * HID), a0);
            body_k1(x0.z, (const float4*)(sW + (kk + 2) * HID), a0);
            body_k1(x0.w, (const float4*)(sW + (kk + 3) * HID), a0);
        }
        for (k = peel + 4 * main4; k < IN_F; k++)
            body_k1(f0[k], (const float4*)(sW + k * HID), a0);
        store_row(r0, a0);
    }
}

__global__ void scatter1_kernel(const long long* __restrict__ ei) {
    int e = blockIdx.x * blockDim.x + threadIdx.x;
    if (e >= N_EDGES) return;
    int s, d;
    load_edge(ei, e, s, d);
    const float4* xs = reinterpret_cast<const float4*>(g_x1 + (long long)s * HID);
    float4 v0 = __ldg(xs + 0), v1 = __ldg(xs + 1);
    float4 v2 = __ldg(xs + 2), v3 = __ldg(xs + 3);
    float* b = g_agg1 + (long long)d * HID;
    red_v4(b + 0, v0);
    red_v4(b + 4, v1);
    red_v4(b + 8, v2);
    red_v4(b + 12, v3);
}

// h = relu(agg1*nd + b1); x2 = (h*ns) @ W2 (padded to 8, col 7 = 0)
__global__ void post1_kernel(const float* __restrict__ b1,
                             const float* __restrict__ W2) {
    __shared__ float sW2[HID * OUTF];
    __shared__ float sb1[HID];
    if (threadIdx.x < HID * OUTF) sW2[threadIdx.x] = W2[threadIdx.x];
    if (threadIdx.x < HID) sb1[threadIdx.x] = b1[threadIdx.x];
    __syncthreads();

    int i = blockIdx.x * blockDim.x + threadIdx.x;
    if (i >= N_NODES) return;
    float nd = g_norm_dst[i], ns = g_norm_src[i];
    const float4* ag = reinterpret_cast<const float4*>(g_agg1 + (long long)i * HID);
    float h[HID];
#pragma unroll
    for (int q = 0; q < 4; q++) {
        float4 v = ag[q];
        h[4 * q + 0] = fmaxf(v.x * nd + sb1[4 * q + 0], 0.f) * ns;
        h[4 * q + 1] = fmaxf(v.y * nd + sb1[4 * q + 1], 0.f) * ns;
        h[4 * q + 2] = fmaxf(v.z * nd + sb1[4 * q + 2], 0.f) * ns;
        h[4 * q + 3] = fmaxf(v.w * nd + sb1[4 * q + 3], 0.f) * ns;
    }
    float o[OUTP];
#pragma unroll
    for (int j = 0; j < OUTP; j++) o[j] = 0.f;
#pragma unroll
    for (int k = 0; k < HID; k++) {
        float hv = h[k];
#pragma unroll
        for (int j = 0; j < OUTF; j++) o[j] += hv * sW2[k * OUTF + j];
    }
    float4* xo = reinterpret_cast<float4*>(g_x2 + (long long)i * OUTP);
    xo[0] = make_float4(o[0], o[1], o[2], o[3]);
    xo[1] = make_float4(o[4], o[5], o[6], 0.f);
}

__global__ void scatter2_kernel(const long long* __restrict__ ei) {
    int e = blockIdx.x * blockDim.x + threadIdx.x;
    if (e >= N_EDGES) return;
    int s, d;
    load_edge(ei, e, s, d);
    const float4* xs = reinterpret_cast<const float4*>(g_x2 + (long long)s * OUTP);
    float4 v0 = __ldg(xs + 0), v1 = __ldg(xs + 1);
    float* b = g_agg2 + (long long)d * OUTP;
    red_v4(b + 0, v0);
    red_v4(b + 4, v1);
}

__global__ void out_kernel(float* __restrict__ out,
                           const float* __restrict__ b2) {
    int idx = blockIdx.x * blockDim.x + threadIdx.x;
    if (idx >= N_NODES * OUTF) return;
    int node = idx / OUTF;
    int j = idx - node * OUTF;
    out[idx] = g_agg2[node * OUTP + j] * g_norm_dst[node] + b2[j];
}

// ---------------- launch -----------------------------------------------------
extern "C" void kernel_launch(void* const* d_in, const int* in_sizes, int n_in,
                              void* d_out, int out_size) {
    const float* feat = (const float*)d_in[0];
    const long long* ei = (const long long*)d_in[1];
    const float* W1 = (const float*)d_in[2];
    const float* b1 = (const float*)d_in[3];
    const float* W2 = (const float*)d_in[4];
    const float* b2 = (const float*)d_in[5];
    float* out = (float*)d_out;

    (void)in_sizes; (void)n_in; (void)out_size;

    zero_kernel<<<960, 256>>>();
    detect_kernel<<<1, 1>>>((const unsigned long long*)ei);
    degree_kernel<<<(N_EDGES + 255) / 256, 256>>>(ei);
    norm_kernel<<<(N_NODES + 255) / 256, 256>>>();

    const int smem = IN_F * HID * 4;  // 91712 B
    cudaFuncSetAttribute(gemm1_kernel,
                         cudaFuncAttributeMaxDynamicSharedMemorySize, smem);
    gemm1_kernel<<<G1_GRID, G1_THREADS, smem>>>(feat, W1);

    scatter1_kernel<<<(N_EDGES + 255) / 256, 256>>>(ei);
    post1_kernel<<<(N_NODES + 255) / 256, 256>>>(b1, W2);
    scatter2_kernel<<<(N_EDGES + 255) / 256, 256>>>(ei);
    out_kernel<<<(N_NODES * OUTF + 255) / 256, 256>>>(out, b2);
}

// round 8
// speedup vs baseline: 3.7780x; 1.4942x over previous
#include <cuda_runtime.h>
#include <cstdint>

#define N_NODES 100000
#define N_EDGES 3200000
#define IN_F    1433
#define HID     16
#define OUTF    7
#define OUTP    8

#define G1_THREADS 512
#define G1_ROWS    676   // 148 * 676 = 100048 >= N_NODES
#define G1_GRID    148
#define G1_PAD     33    // smem row stride (floats) for staged features

#define SCAN_BLK  1024
#define SCAN_NBLK 98     // 98*1024 = 100352 >= N_NODES

// ---------------- scratch (static device globals; no allocation) ------------
__device__ __align__(16) float g_norm_src[N_NODES];
__device__ __align__(16) float g_norm_dst[N_NODES];
__device__ __align__(16) int   g_deg_out[N_NODES];
__device__ __align__(16) int   g_deg_in [N_NODES];
__device__ __align__(16) int   g_intra  [N_NODES];      // intra-block excl scan
__device__ int   g_bsum[SCAN_NBLK];
__device__ int   g_boff[SCAN_NBLK];
__device__ __align__(16) int   g_off   [N_NODES + 1];   // CSR row offsets (by dst)
__device__ __align__(16) int   g_cursor[N_NODES];
__device__ __align__(16) int   g_csr_src[N_EDGES];      // src ids grouped by dst
__device__ __align__(16) float g_x1[N_NODES * HID];     // (X*ns)@W1
__device__ __align__(16) float g_x2[N_NODES * OUTP];    // (h*ns)@W2, padded
__device__ int g_is64;

// ---------------- small PTX helpers ----------------------------------------
__device__ __forceinline__ unsigned long long pk2(float lo, float hi) {
    unsigned long long r;
    asm("mov.b64 %0, {%1, %2};" : "=l"(r) : "f"(lo), "f"(hi));
    return r;
}
__device__ __forceinline__ float2 upk2(unsigned long long v) {
    float2 f;
    asm("mov.b64 {%0, %1}, %2;" : "=f"(f.x), "=f"(f.y) : "l"(v));
    return f;
}
__device__ __forceinline__ void fma2(unsigned long long& a,
                                     unsigned long long x,
                                     unsigned long long w) {
    asm("fma.rn.f32x2 %0, %1, %2, %0;" : "+l"(a) : "l"(x), "l"(w));
}

// ---------------- setup kernels ---------------------------------------------
__global__ void zero_kernel() {
    int i = blockIdx.x * blockDim.x + threadIdx.x;
    if (i < N_NODES) { g_deg_out[i] = 0; g_deg_in[i] = 0; }
}

// Detect whether edge_index is genuinely int64 or int32 (JAX x64 disabled).
__global__ void detect_kernel(const unsigned long long* __restrict__ ei) {
    unsigned long long mx = 0;
#pragma unroll
    for (int i = 0; i < 16; i++) mx = mx < ei[i] ? ei[i] : mx;
    g_is64 = (mx < (1ull << 32)) ? 1 : 0;
}

__device__ __forceinline__ void load_edge(const long long* ei, int e,
                                          int& s, int& d) {
    if (g_is64) {
        s = (int)ei[e];
        d = (int)ei[N_EDGES + e];
    } else {
        const int* e32 = reinterpret_cast<const int*>(ei);
        s = e32[e];
        d = e32[N_EDGES + e];
    }
}

__global__ void degree_kernel(const long long* __restrict__ ei) {
    int e = blockIdx.x * blockDim.x + threadIdx.x;
    if (e >= N_EDGES) return;
    int s, d;
    load_edge(ei, e, s, d);
    atomicAdd(g_deg_out + s, 1);
    atomicAdd(g_deg_in + d, 1);
}

__global__ void norm_kernel() {
    int i = blockIdx.x * blockDim.x + threadIdx.x;
    if (i >= N_NODES) return;
    g_norm_src[i] = rsqrtf(fmaxf((float)g_deg_out[i], 1.f));
    g_norm_dst[i] = rsqrtf(fmaxf((float)g_deg_in[i], 1.f));
}

// ---------------- prefix sum over deg_in -> g_off ---------------------------
__global__ void scan1_kernel() {
    __shared__ int tmp[SCAN_BLK];
    int t = threadIdx.x;
    int i = blockIdx.x * SCAN_BLK + t;
    int v = (i < N_NODES) ? g_deg_in[i] : 0;
    tmp[t] = v;
    __syncthreads();
#pragma unroll
    for (int off = 1; off < SCAN_BLK; off <<= 1) {
        int a = (t >= off) ? tmp[t - off] : 0;
        __syncthreads();
        tmp[t] += a;
        __syncthreads();
    }
    if (i < N_NODES) g_intra[i] = tmp[t] - v;   // exclusive
    if (t == SCAN_BLK - 1) g_bsum[blockIdx.x] = tmp[t];
}

__global__ void scan2_kernel() {
    __shared__ int tmp[128];
    int t = threadIdx.x;
    int v = (t < SCAN_NBLK) ? g_bsum[t] : 0;
    tmp[t] = v;
    __syncthreads();
#pragma unroll
    for (int off = 1; off < 128; off <<= 1) {
        int a = (t >= off) ? tmp[t - off] : 0;
        __syncthreads();
        tmp[t] += a;
        __syncthreads();
    }
    if (t < SCAN_NBLK) g_boff[t] = tmp[t] - v;  // exclusive
    if (t == 127) g_off[N_NODES] = tmp[127];    // == N_EDGES
}

__global__ void scan3_kernel() {
    int i = blockIdx.x * blockDim.x + threadIdx.x;
    if (i >= N_NODES) return;
    int v = g_boff[i >> 10] + g_intra[i];
    g_off[i] = v;
    g_cursor[i] = v;
}

__global__ void fill_kernel(const long long* __restrict__ ei) {
    int e = blockIdx.x * blockDim.x + threadIdx.x;
    if (e >= N_EDGES) return;
    int s, d;
    load_edge(ei, e, s, d);
    int pos = atomicAdd(g_cursor + d, 1);
    g_csr_src[pos] = s;
}

// -------- gemm1: x1[r][0:16] = norm_src[r] * (feat[r,:] @ W1) ---------------
// 148 CTAs (1/SM), 512 threads. W1 (91.7KB) + staged feature chunk
// (676 rows x 32 floats padded to 33 = 89.2KB) both in dynamic smem.
// Chunk loads are coalesced scalar LDG; compute reads are conflict-free LDS.

__device__ __forceinline__ void body2(float x0, float x1v,
                                      const ulonglong2* __restrict__ wk,
                                      unsigned long long* a0,
                                      unsigned long long* a1) {
    unsigned long long p0 = pk2(x0, x0);
    unsigned long long p1 = pk2(x1v, x1v);
#pragma unroll
    for (int q = 0; q < 4; q++) {
        ulonglong2 u = wk[q];
        fma2(a0[2 * q],     p0, u.x);
        fma2(a0[2 * q + 1], p0, u.y);
        fma2(a1[2 * q],     p1, u.x);
        fma2(a1[2 * q + 1], p1, u.y);
    }
}
__device__ __forceinline__ void body1(float x0,
                                      const ulonglong2* __restrict__ wk,
                                      unsigned long long* a0) {
    unsigned long long p0 = pk2(x0, x0);
#pragma unroll
    for (int q = 0; q < 4; q++) {
        ulonglong2 u = wk[q];
        fma2(a0[2 * q],     p0, u.x);
        fma2(a0[2 * q + 1], p0, u.y);
    }
}

__device__ __forceinline__ void store_row(int r, unsigned long long* a) {
    float ns = g_norm_src[r];
    float4* o = reinterpret_cast<float4*>(g_x1 + (long long)r * HID);
#pragma unroll
    for (int jj = 0; jj < 4; jj++) {
        float2 e0 = upk2(a[2 * jj]), e1 = upk2(a[2 * jj + 1]);
        o[jj] = make_float4(e0.x * ns, e0.y * ns, e1.x * ns, e1.y * ns);
    }
}

__global__ void __launch_bounds__(G1_THREADS, 1)
gemm1_kernel(const float* __restrict__ feat, const float* __restrict__ W1) {
    extern __shared__ float smem[];
    float* sW = smem;                       // IN_F * HID = 22928 floats
    float* sF = smem + IN_F * HID;          // G1_ROWS * G1_PAD = 22308 floats

    for (int i = threadIdx.x; i < IN_F * HID / 4; i += G1_THREADS)
        reinterpret_cast<float4*>(sW)[i] =
            reinterpret_cast<const float4*>(W1)[i];
    __syncthreads();

    const int base  = blockIdx.x * G1_ROWS;
    const int nrows = min(G1_ROWS, N_NODES - base);
    const int tid   = threadIdx.x;
    const bool v0 = tid < nrows;
    const bool v1 = (512 + tid) < nrows;

    unsigned long long a0[8], a1[8];
#pragma unroll
    for (int j = 0; j < 8; j++) { a0[j] = 0ull; a1[j] = 0ull; }

    const int total = nrows * 32;
    for (int K0 = 0; K0 < IN_F; K0 += 32) {
        const int CW = min(32, IN_F - K0);
        // coalesced cooperative load of rows [base, base+nrows) x [K0, K0+CW)
        for (int f = tid; f < total; f += G1_THREADS) {
            int row = f >> 5, kk = f & 31;
            if (kk < CW)
                sF[row * G1_PAD + kk] =
                    feat[(long long)(base + row) * IN_F + K0 + kk];
        }
        __syncthreads();

        if (v1) {
            const float* f0 = sF + tid * G1_PAD;
            const float* f1 = sF + (512 + tid) * G1_PAD;
            if (CW == 32) {
#pragma unroll
                for (int kk = 0; kk < 32; kk++)
                    body2(f0[kk], f1[kk],
                          (const ulonglong2*)(sW + (K0 + kk) * HID), a0, a1);
            } else {
                for (int kk = 0; kk < CW; kk++)
                    body2(f0[kk], f1[kk],
                          (const ulonglong2*)(sW + (K0 + kk) * HID), a0, a1);
            }
        } else if (v0) {
            const float* f0 = sF + tid * G1_PAD;
            if (CW == 32) {
#pragma unroll
                for (int kk = 0; kk < 32; kk++)
                    body1(f0[kk],
                          (const ulonglong2*)(sW + (K0 + kk) * HID), a0);
            } else {
                for (int kk = 0; kk < CW; kk++)
                    body1(f0[kk],
                          (const ulonglong2*)(sW + (K0 + kk) * HID), a0);
            }
        }
        __syncthreads();
    }

    if (v0) store_row(base + tid, a0);
    if (v1) store_row(base + 512 + tid, a1);
}

// -------- gather1 (+ fused relu/bias/W2): per-dst gather-sum of x1 ----------
__global__ void gather1_kernel(const float* __restrict__ b1,
                               const float* __restrict__ W2) {
    __shared__ float sW2[HID * OUTF];
    __shared__ float sb1[HID];
    if (threadIdx.x < HID * OUTF) sW2[threadIdx.x] = W2[threadIdx.x];
    if (threadIdx.x < HID) sb1[threadIdx.x] = b1[threadIdx.x];
    __syncthreads();

    int i = blockIdx.x * blockDim.x + threadIdx.x;
    if (i >= N_NODES) return;
    int p0 = g_off[i], p1 = g_off[i + 1];

    float4 A = make_float4(0.f, 0.f, 0.f, 0.f), B = A, C = A, D = A;
    for (int p = p0; p < p1; p++) {
        int s = g_csr_src[p];
        const float4* xs =
            reinterpret_cast<const float4*>(g_x1 + (long long)s * HID);
        float4 t0 = __ldg(xs + 0), t1 = __ldg(xs + 1);
        float4 t2 = __ldg(xs + 2), t3 = __ldg(xs + 3);
        A.x += t0.x; A.y += t0.y; A.z += t0.z; A.w += t0.w;
        B.x += t1.x; B.y += t1.y; B.z += t1.z; B.w += t1.w;
        C.x += t2.x; C.y += t2.y; C.z += t2.z; C.w += t2.w;
        D.x += t3.x; D.y += t3.y; D.z += t3.z; D.w += t3.w;
    }

    float nd = g_norm_dst[i], ns = g_norm_src[i];
    float h[HID];
    float acc[HID] = { A.x, A.y, A.z, A.w, B.x, B.y, B.z, B.w,
                       C.x, C.y, C.z, C.w, D.x, D.y, D.z, D.w };
#pragma unroll
    for (int k = 0; k < HID; k++)
        h[k] = fmaxf(acc[k] * nd + sb1[k], 0.f) * ns;

    float o[OUTF];
#pragma unroll
    for (int j = 0; j < OUTF; j++) o[j] = 0.f;
#pragma unroll
    for (int k = 0; k < HID; k++) {
        float hv = h[k];
#pragma unroll
        for (int j = 0; j < OUTF; j++) o[j] += hv * sW2[k * OUTF + j];
    }
    float4* xo = reinterpret_cast<float4*>(g_x2 + (long long)i * OUTP);
    xo[0] = make_float4(o[0], o[1], o[2], o[3]);
    xo[1] = make_float4(o[4], o[5], o[6], 0.f);
}

// -------- gather2 (+ fused norm/bias): per-dst gather-sum of x2 -> out ------
__global__ void gather2_kernel(float* __restrict__ out,
                               const float* __restrict__ b2) {
    int i = blockIdx.x * blockDim.x + threadIdx.x;
    if (i >= N_NODES) return;
    int p0 = g_off[i], p1 = g_off[i + 1];

    float4 A = make_float4(0.f, 0.f, 0.f, 0.f), B = A;
    for (int p = p0; p < p1; p++) {
        int s = g_csr_src[p];
        const float4* xs =
            reinterpret_cast<const float4*>(g_x2 + (long long)s * OUTP);
        float4 t0 = __ldg(xs + 0), t1 = __ldg(xs + 1);
        A.x += t0.x; A.y += t0.y; A.z += t0.z; A.w += t0.w;
        B.x += t1.x; B.y += t1.y; B.z += t1.z;
    }
    float nd = g_norm_dst[i];
    float* o = out + (long long)i * OUTF;
    o[0] = A.x * nd + __ldg(b2 + 0);
    o[1] = A.y * nd + __ldg(b2 + 1);
    o[2] = A.z * nd + __ldg(b2 + 2);
    o[3] = A.w * nd + __ldg(b2 + 3);
    o[4] = B.x * nd + __ldg(b2 + 4);
    o[5] = B.y * nd + __ldg(b2 + 5);
    o[6] = B.z * nd + __ldg(b2 + 6);
}

// ---------------- launch -----------------------------------------------------
extern "C" void kernel_launch(void* const* d_in, const int* in_sizes, int n_in,
                              void* d_out, int out_size) {
    const float* feat = (const float*)d_in[0];
    const long long* ei = (const long long*)d_in[1];
    const float* W1 = (const float*)d_in[2];
    const float* b1 = (const float*)d_in[3];
    const float* W2 = (const float*)d_in[4];
    const float* b2 = (const float*)d_in[5];
    float* out = (float*)d_out;

    (void)in_sizes; (void)n_in; (void)out_size;

    zero_kernel<<<(N_NODES + 255) / 256, 256>>>();
    detect_kernel<<<1, 1>>>((const unsigned long long*)ei);
    degree_kernel<<<(N_EDGES + 255) / 256, 256>>>(ei);
    norm_kernel<<<(N_NODES + 255) / 256, 256>>>();

    scan1_kernel<<<SCAN_NBLK, SCAN_BLK>>>();
    scan2_kernel<<<1, 128>>>();
    scan3_kernel<<<(N_NODES + 255) / 256, 256>>>();
    fill_kernel<<<(N_EDGES + 255) / 256, 256>>>(ei);

    const int smem = (IN_F * HID + G1_ROWS * G1_PAD) * 4;  // 180944 B
    cudaFuncSetAttribute(gemm1_kernel,
                         cudaFuncAttributeMaxDynamicSharedMemorySize, smem);
    gemm1_kernel<<<G1_GRID, G1_THREADS, smem>>>(feat, W1);

    gather1_kernel<<<(N_NODES + 255) / 256, 256>>>(b1, W2);
    gather2_kernel<<<(N_NODES + 255) / 256, 256>>>(out, b2);
}

// round 10
// speedup vs baseline: 3.8354x; 1.0152x over previous
#include <cuda_runtime.h>
#include <cstdint>

#define N_NODES 100000
#define N_EDGES 3200000
#define IN_F    1433
#define HID     16
#define OUTF    7
#define OUTP    8

#define G1_THREADS 512
#define G1_ROWS    676   // 148 * 676 = 100048 >= N_NODES
#define G1_GRID    148
#define G1_PAD     33    // smem row stride (floats) for staged features
#define NCHUNK     45    // ceil(1433/32)
#define NSTAGE     43    // ceil(676*32/512)

#define SCAN_BLK  1024
#define SCAN_NBLK 98     // 98*1024 = 100352 >= N_NODES

// ---------------- scratch (static device globals; no allocation) ------------
__device__ __align__(16) float g_norm_src[N_NODES];
__device__ __align__(16) float g_norm_dst[N_NODES];
__device__ __align__(16) int   g_deg_out[N_NODES];
__device__ __align__(16) int   g_deg_in [N_NODES];
__device__ __align__(16) int   g_intra  [N_NODES];      // intra-block excl scan
__device__ int   g_bsum[SCAN_NBLK];
__device__ int   g_boff[SCAN_NBLK];
__device__ __align__(16) int   g_off   [N_NODES + 1];   // CSR row offsets (by dst)
__device__ __align__(16) int   g_cursor[N_NODES];
__device__ __align__(16) int   g_csr_src[N_EDGES];      // src ids grouped by dst
__device__ __align__(16) float g_x1[N_NODES * HID];     // (X*ns)@W1
__device__ __align__(16) float g_x2[N_NODES * OUTP];    // (h*ns)@W2, padded
__device__ int g_is64;

// ---------------- small PTX helpers ----------------------------------------
__device__ __forceinline__ unsigned long long pk2(float lo, float hi) {
    unsigned long long r;
    asm("mov.b64 %0, {%1, %2};" : "=l"(r) : "f"(lo), "f"(hi));
    return r;
}
__device__ __forceinline__ float2 upk2(unsigned long long v) {
    float2 f;
    asm("mov.b64 {%0, %1}, %2;" : "=f"(f.x), "=f"(f.y) : "l"(v));
    return f;
}
__device__ __forceinline__ void fma2(unsigned long long& a,
                                     unsigned long long x,
                                     unsigned long long w) {
    asm("fma.rn.f32x2 %0, %1, %2, %0;" : "+l"(a) : "l"(x), "l"(w));
}

// ---------------- setup -----------------------------------------------------
__global__ void zero_detect_kernel(const unsigned long long* __restrict__ ei) {
    int i = blockIdx.x * blockDim.x + threadIdx.x;
    if (i < N_NODES) { g_deg_out[i] = 0; g_deg_in[i] = 0; }
    if (i == 0) {
        unsigned long long mx = 0;
#pragma unroll
        for (int j = 0; j < 16; j++) mx = mx < ei[j] ? ei[j] : mx;
        g_is64 = (mx < (1ull << 32)) ? 1 : 0;
    }
}

__device__ __forceinline__ void load_edge(const long long* ei, int e,
                                          int& s, int& d) {
    if (g_is64) {
        s = (int)ei[e];
        d = (int)ei[N_EDGES + e];
    } else {
        const int* e32 = reinterpret_cast<const int*>(ei);
        s = e32[e];
        d = e32[N_EDGES + e];
    }
}

__global__ void degree_kernel(const long long* __restrict__ ei) {
    int e = blockIdx.x * blockDim.x + threadIdx.x;
    if (e >= N_EDGES) return;
    int s, d;
    load_edge(ei, e, s, d);
    atomicAdd(g_deg_out + s, 1);
    atomicAdd(g_deg_in + d, 1);
}

// scan over deg_in (block-level) + fused norm computation
__global__ void scan1_kernel() {
    __shared__ int tmp[SCAN_BLK];
    int t = threadIdx.x;
    int i = blockIdx.x * SCAN_BLK + t;
    int v = (i < N_NODES) ? g_deg_in[i] : 0;
    if (i < N_NODES) {
        g_norm_src[i] = rsqrtf(fmaxf((float)g_deg_out[i], 1.f));
        g_norm_dst[i] = rsqrtf(fmaxf((float)v, 1.f));
    }
    tmp[t] = v;
    __syncthreads();
#pragma unroll
    for (int off = 1; off < SCAN_BLK; off <<= 1) {
        int a = (t >= off) ? tmp[t - off] : 0;
        __syncthreads();
        tmp[t] += a;
        __syncthreads();
    }
    if (i < N_NODES) g_intra[i] = tmp[t] - v;   // exclusive
    if (t == SCAN_BLK - 1) g_bsum[blockIdx.x] = tmp[t];
}

__global__ void scan2_kernel() {
    __shared__ int tmp[128];
    int t = threadIdx.x;
    int v = (t < SCAN_NBLK) ? g_bsum[t] : 0;
    tmp[t] = v;
    __syncthreads();
#pragma unroll
    for (int off = 1; off < 128; off <<= 1) {
        int a = (t >= off) ? tmp[t - off] : 0;
        __syncthreads();
        tmp[t] += a;
        __syncthreads();
    }
    if (t < SCAN_NBLK) g_boff[t] = tmp[t] - v;  // exclusive
    if (t == 127) g_off[N_NODES] = tmp[127];    // == N_EDGES
}

__global__ void scan3_kernel() {
    int i = blockIdx.x * blockDim.x + threadIdx.x;
    if (i >= N_NODES) return;
    int v = g_boff[i >> 10] + g_intra[i];
    g_off[i] = v;
    g_cursor[i] = v;
}

__global__ void fill_kernel(const long long* __restrict__ ei) {
    int e = blockIdx.x * blockDim.x + threadIdx.x;
    if (e >= N_EDGES) return;
    int s, d;
    load_edge(ei, e, s, d);
    int pos = atomicAdd(g_cursor + d, 1);
    g_csr_src[pos] = s;
}

// -------- gemm1: x1[r][0:16] = norm_src[r] * (feat[r,:] @ W1) ---------------
// 148 CTAs (1/SM), 512 threads. W1 in smem; feature chunks double-buffered:
// registers stage chunk c+1 (coalesced LDG) while FFMA2 consumes chunk c from
// smem; STS after compute. One smem feature buffer, registers are buffer 2.

__device__ __forceinline__ void body2(float x0, float x1v,
                                      const ulonglong2* __restrict__ wk,
                                      unsigned long long* a0,
                                      unsigned long long* a1) {
    unsigned long long p0 = pk2(x0, x0);
    unsigned long long p1 = pk2(x1v, x1v);
#pragma unroll
    for (int q = 0; q < 4; q++) {
        ulonglong2 u = wk[q];
        fma2(a0[2 * q],     p0, u.x);
        fma2(a0[2 * q + 1], p0, u.y);
        fma2(a1[2 * q],     p1, u.x);
        fma2(a1[2 * q + 1], p1, u.y);
    }
}
__device__ __forceinline__ void body1(float x0,
                                      const ulonglong2* __restrict__ wk,
                                      unsigned long long* a0) {
    unsigned long long p0 = pk2(x0, x0);
#pragma unroll
    for (int q = 0; q < 4; q++) {
        ulonglong2 u = wk[q];
        fma2(a0[2 * q],     p0, u.x);
        fma2(a0[2 * q + 1], p0, u.y);
    }
}

__device__ __forceinline__ void store_row(int r, unsigned long long* a) {
    float ns = g_norm_src[r];
    float4* o = reinterpret_cast<float4*>(g_x1 + (long long)r * HID);
#pragma unroll
    for (int jj = 0; jj < 4; jj++) {
        float2 e0 = upk2(a[2 * jj]), e1 = upk2(a[2 * jj + 1]);
        o[jj] = make_float4(e0.x * ns, e0.y * ns, e1.x * ns, e1.y * ns);
    }
}

__global__ void __launch_bounds__(G1_THREADS, 1)
gemm1_kernel(const float* __restrict__ feat, const float* __restrict__ W1) {
    extern __shared__ float smem[];
    float* sW = smem;                       // IN_F * HID = 22928 floats
    float* sF = smem + IN_F * HID;          // G1_ROWS * G1_PAD = 22308 floats

    const int tid = threadIdx.x;
    for (int i = tid; i < IN_F * HID / 4; i += G1_THREADS)
        reinterpret_cast<float4*>(sW)[i] =
            reinterpret_cast<const float4*>(W1)[i];

    const int base  = blockIdx.x * G1_ROWS;
    const int nrows = min(G1_ROWS, N_NODES - base);
    const int total = nrows * 32;
    const bool v1 = (512 + tid) < nrows;    // v0 always true (nrows >= 628)
    const float* fb = feat + (long long)base * IN_F;

    unsigned long long a0[8], a1[8];
#pragma unroll
    for (int j = 0; j < 8; j++) { a0[j] = 0ull; a1[j] = 0ull; }

    float r[NSTAGE];
    // stage chunk 0
#pragma unroll
    for (int u = 0; u < NSTAGE; u++) {
        int f = tid + u * G1_THREADS;
        int row = f >> 5, kk = f & 31;
        r[u] = (f < total) ? fb[(long long)row * IN_F + kk] : 0.f;
    }
    __syncthreads();    // sW visible; sF untouched yet
#pragma unroll
    for (int u = 0; u < NSTAGE; u++) {
        int f = tid + u * G1_THREADS;
        if (f < total) sF[(f >> 5) * G1_PAD + (f & 31)] = r[u];
    }
    __syncthreads();

    for (int c = 0; c < NCHUNK; c++) {
        const int K0n = (c + 1) * 32;
        if (c + 1 < NCHUNK) {
            const int CWn = min(32, IN_F - K0n);
#pragma unroll
            for (int u = 0; u < NSTAGE; u++) {
                int f = tid + u * G1_THREADS;
                int row = f >> 5, kk = f & 31;
                r[u] = (f < total && kk < CWn)
                     ? fb[(long long)row * IN_F + K0n + kk] : 0.f;
            }
        }

        const int K0 = c * 32;
        const int CW = min(32, IN_F - K0);
        const float* f0 = sF + tid * G1_PAD;
        const float* f1 = sF + (512 + tid) * G1_PAD;
        if (v1) {
            if (CW == 32) {
#pragma unroll
                for (int kk = 0; kk < 32; kk++)
                    body2(f0[kk], f1[kk],
                          (const ulonglong2*)(sW + (K0 + kk) * HID), a0, a1);
            } else {
                for (int kk = 0; kk < CW; kk++)
                    body2(f0[kk], f1[kk],
                          (const ulonglong2*)(sW + (K0 + kk) * HID), a0, a1);
            }
        } else {
            if (CW == 32) {
#pragma unroll
                for (int kk = 0; kk < 32; kk++)
                    body1(f0[kk],
                          (const ulonglong2*)(sW + (K0 + kk) * HID), a0);
            } else {
                for (int kk = 0; kk < CW; kk++)
                    body1(f0[kk],
                          (const ulonglong2*)(sW + (K0 + kk) * HID), a0);
            }
        }
        __syncthreads();

        if (c + 1 < NCHUNK) {
            const int CWn = min(32, IN_F - K0n);
#pragma unroll
            for (int u = 0; u < NSTAGE; u++) {
                int f = tid + u * G1_THREADS;
                int kk = f & 31;
                if (f < total && kk < CWn)
                    sF[(f >> 5) * G1_PAD + kk] = r[u];
            }
            __syncthreads();
        }
    }

    store_row(base + tid, a0);
    if (v1) store_row(base + 512 + tid, a1);
}

// -------- gather1 (+ fused relu/bias/W2): per-dst gather-sum of x1 ----------
__global__ void gather1_kernel(const float* __restrict__ b1,
                               const float* __restrict__ W2) {
    __shared__ float sW2[HID * OUTF];
    __shared__ float sb1[HID];
    if (threadIdx.x < HID * OUTF) sW2[threadIdx.x] = W2[threadIdx.x];
    if (threadIdx.x < HID) sb1[threadIdx.x] = b1[threadIdx.x];
    __syncthreads();

    int i = blockIdx.x * blockDim.x + threadIdx.x;
    if (i >= N_NODES) return;
    int p0 = g_off[i], p1 = g_off[i + 1];

    float4 A = make_float4(0.f, 0.f, 0.f, 0.f), B = A, C = A, D = A;
    for (int p = p0; p < p1; p++) {
        int s = g_csr_src[p];
        const float4* xs =
            reinterpret_cast<const float4*>(g_x1 + (long long)s * HID);
        float4 t0 = __ldg(xs + 0), t1 = __ldg(xs + 1);
        float4 t2 = __ldg(xs + 2), t3 = __ldg(xs + 3);
        A.x += t0.x; A.y += t0.y; A.z += t0.z; A.w += t0.w;
        B.x += t1.x; B.y += t1.y; B.z += t1.z; B.w += t1.w;
        C.x += t2.x; C.y += t2.y; C.z += t2.z; C.w += t2.w;
        D.x += t3.x; D.y += t3.y; D.z += t3.z; D.w += t3.w;
    }

    float nd = g_norm_dst[i], ns = g_norm_src[i];
    float h[HID];
    float acc[HID] = { A.x, A.y, A.z, A.w, B.x, B.y, B.z, B.w,
                       C.x, C.y, C.z, C.w, D.x, D.y, D.z, D.w };
#pragma unroll
    for (int k = 0; k < HID; k++)
        h[k] = fmaxf(acc[k] * nd + sb1[k], 0.f) * ns;

    float o[OUTF];
#pragma unroll
    for (int j = 0; j < OUTF; j++) o[j] = 0.f;
#pragma unroll
    for (int k = 0; k < HID; k++) {
        float hv = h[k];
#pragma unroll
        for (int j = 0; j < OUTF; j++) o[j] += hv * sW2[k * OUTF + j];
    }
    float4* xo = reinterpret_cast<float4*>(g_x2 + (long long)i * OUTP);
    xo[0] = make_float4(o[0], o[1], o[2], o[3]);
    xo[1] = make_float4(o[4], o[5], o[6], 0.f);
}

// -------- gather2 (+ fused norm/bias): per-dst gather-sum of x2 -> out ------
__global__ void gather2_kernel(float* __restrict__ out,
                               const float* __restrict__ b2) {
    int i = blockIdx.x * blockDim.x + threadIdx.x;
    if (i >= N_NODES) return;
    int p0 = g_off[i], p1 = g_off[i + 1];

    float4 A = make_float4(0.f, 0.f, 0.f, 0.f), B = A;
    for (int p = p0; p < p1; p++) {
        int s = g_csr_src[p];
        const float4* xs =
            reinterpret_cast<const float4*>(g_x2 + (long long)s * OUTP);
        float4 t0 = __ldg(xs + 0), t1 = __ldg(xs + 1);
        A.x += t0.x; A.y += t0.y; A.z += t0.z; A.w += t0.w;
        B.x += t1.x; B.y += t1.y; B.z += t1.z;
    }
    float nd = g_norm_dst[i];
    float* o = out + (long long)i * OUTF;
    o[0] = A.x * nd + __ldg(b2 + 0);
    o[1] = A.y * nd + __ldg(b2 + 1);
    o[2] = A.z * nd + __ldg(b2 + 2);
    o[3] = A.w * nd + __ldg(b2 + 3);
    o[4] = B.x * nd + __ldg(b2 + 4);
    o[5] = B.y * nd + __ldg(b2 + 5);
    o[6] = B.z * nd + __ldg(b2 + 6);
}

// ---------------- launch -----------------------------------------------------
// Order chosen so gemm1 is the 4th launch (ncu empirically captures launch #4).
extern "C" void kernel_launch(void* const* d_in, const int* in_sizes, int n_in,
                              void* d_out, int out_size) {
    const float* feat = (const float*)d_in[0];
    const long long* ei = (const long long*)d_in[1];
    const float* W1 = (const float*)d_in[2];
    const float* b1 = (const float*)d_in[3];
    const float* W2 = (const float*)d_in[4];
    const float* b2 = (const float*)d_in[5];
    float* out = (float*)d_out;

    (void)in_sizes; (void)n_in; (void)out_size;

    zero_detect_kernel<<<(N_NODES + 255) / 256, 256>>>(
        (const unsigned long long*)ei);
    degree_kernel<<<(N_EDGES + 255) / 256, 256>>>(ei);
    scan1_kernel<<<SCAN_NBLK, SCAN_BLK>>>();   // + fused norm computation

    const int smem = (IN_F * HID + G1_ROWS * G1_PAD) * 4;  // 180944 B
    cudaFuncSetAttribute(gemm1_kernel,
                         cudaFuncAttributeMaxDynamicSharedMemorySize, smem);
    gemm1_kernel<<<G1_GRID, G1_THREADS, smem>>>(feat, W1);

    scan2_kernel<<<1, 128>>>();
    scan3_kernel<<<(N_NODES + 255) / 256, 256>>>();
    fill_kernel<<<(N_EDGES + 255) / 256, 256>>>(ei);

    gather1_kernel<<<(N_NODES + 255) / 256, 256>>>(b1, W2);
    gather2_kernel<<<(N_NODES + 255) / 256, 256>>>(out, b2);
}